// round 12
// baseline (speedup 1.0000x reference)
#include <cuda_runtime.h>

#define B_ 8
#define L_ 2048
#define D_ 1024
#define Z_ 128
#define V_ 2048
#define NEMA 16
#define BLROWS (B_*L_)            /* 16384 */
#define MXCOLS (Z_ + V_ + 2*D_)   /* 4224  */
#define ECHUNK 256

// ---------------------------------------------------------------------------
// Scratch (static device allocation; no cudaMalloc allowed)
// layout (float offsets):
//   xn    @ 0          16777216   (BL*D)
//   mx    @ 16777216   16777216
//   v     @ 33554432   33554432   (BL*V)
//   base  @ 67108864   69206016   (BL*4224)
//   qh    @ 136314880  2097152    (B*L*Z)
//   khT   @ 138412032  2097152
//   qk    @ 140509184  33554432   (B*L*L)
//   h     @ 174063616  33554432
//   h2    @ 207618048  16777216
//   out   @ 224395264  16777216
//   yn    @ 241172480  16777216
//   f1    @ 257949696  33554432
//   c     @ 291504128  16384
//   q     @ 291520512  16384
// ---------------------------------------------------------------------------
__device__ float g_scratch[291536896];

__device__ __forceinline__ float siluf(float x){ return x / (1.f + __expf(-x)); }
__device__ __forceinline__ float sigmf(float x){ return 1.f / (1.f + __expf(-x)); }

// ---------------------------------------------------------------------------
// LayerNorm over D=1024; one block per row, 256 threads * float4
// ---------------------------------------------------------------------------
__global__ void layernorm_k(const float* __restrict__ x, const float* __restrict__ w,
                            const float* __restrict__ b, float* __restrict__ o){
    long row = blockIdx.x;
    int t = threadIdx.x;
    float4 xv = reinterpret_cast<const float4*>(x + row*D_)[t];
    float s  = xv.x+xv.y+xv.z+xv.w;
    float s2 = xv.x*xv.x+xv.y*xv.y+xv.z*xv.z+xv.w*xv.w;
    #pragma unroll
    for(int off=16; off>0; off>>=1){
        s  += __shfl_xor_sync(0xffffffffu, s,  off);
        s2 += __shfl_xor_sync(0xffffffffu, s2, off);
    }
    __shared__ float ss[8], ss2[8];
    __shared__ float smu, sinv;
    if((t&31)==0){ ss[t>>5]=s; ss2[t>>5]=s2; }
    __syncthreads();
    if(t==0){
        float S=0.f, S2=0.f;
        #pragma unroll
        for(int i=0;i<8;i++){ S+=ss[i]; S2+=ss2[i]; }
        float mu  = S*(1.f/D_);
        float var = S2*(1.f/D_) - mu*mu;
        smu = mu; sinv = rsqrtf(var + 1e-5f);
    }
    __syncthreads();
    float mu = smu, inv = sinv;
    float4 wv = reinterpret_cast<const float4*>(w)[t];
    float4 bv = reinterpret_cast<const float4*>(b)[t];
    float4 ov;
    ov.x = (xv.x-mu)*inv*wv.x + bv.x;
    ov.y = (xv.y-mu)*inv*wv.y + bv.y;
    ov.z = (xv.z-mu)*inv*wv.z + bv.z;
    ov.w = (xv.w-mu)*inv*wv.w + bv.w;
    reinterpret_cast<float4*>(o + row*D_)[t] = ov;
}

// ---------------------------------------------------------------------------
// EMA coefficients: c = p*beta*gamma/sqrt(N), q = 1 - p*sigmoid(alpha)
// ---------------------------------------------------------------------------
__global__ void emacoef_k(const float* __restrict__ delta, const float* __restrict__ alpha,
                          const float* __restrict__ beta,  const float* __restrict__ gamma,
                          float* __restrict__ c, float* __restrict__ q){
    int i = blockIdx.x*256 + threadIdx.x;   // D*N = 16384
    float p = sigmf(delta[i]);
    q[i] = 1.f - p*sigmf(alpha[i]);
    c[i] = p*beta[i]*gamma[i]*0.25f;        // 1/sqrt(16)
}

// ---------------------------------------------------------------------------
// EMA scan (replaces the FFT conv) fused with mx = silu(ema + xn*omega).
// Chunked: each thread owns (b,d,chunk); 256-step warm-up re-establishes the
// state (truncation <= q^256 <= 1e-11 for this data).
// ---------------------------------------------------------------------------
__global__ void emascan_k(const float* __restrict__ xn, const float* __restrict__ cArr,
                          const float* __restrict__ qArr, const float* __restrict__ omega,
                          float* __restrict__ mx){
    int d = blockIdx.x*256 + threadIdx.x;
    int chunk = blockIdx.y;
    int b = blockIdx.z;
    float c[NEMA], q[NEMA], s[NEMA];
    #pragma unroll
    for(int n=0;n<NEMA;n++){ c[n]=cArr[d*NEMA+n]; q[n]=qArr[d*NEMA+n]; s[n]=0.f; }
    float om = omega[d];
    int start = chunk*ECHUNK;
    int l0 = start - ECHUNK; if(l0 < 0) l0 = 0;
    const float* xp = xn + ((long)b*L_ + l0)*D_ + d;
    for(int l=l0; l<start; l++){
        float xv = *xp; xp += D_;
        #pragma unroll
        for(int n=0;n<NEMA;n++) s[n] = fmaf(q[n], s[n], xv);
    }
    float* mp = mx + ((long)b*L_ + start)*D_ + d;
    for(int l=0; l<ECHUNK; l++){
        float xv = *xp; xp += D_;
        float a0=0.f,a1=0.f,a2=0.f,a3=0.f;
        #pragma unroll
        for(int n=0;n<NEMA;n+=4){
            s[n]   = fmaf(q[n],   s[n],   xv);
            s[n+1] = fmaf(q[n+1], s[n+1], xv);
            s[n+2] = fmaf(q[n+2], s[n+2], xv);
            s[n+3] = fmaf(q[n+3], s[n+3], xv);
            a0 = fmaf(c[n],   s[n],   a0);
            a1 = fmaf(c[n+1], s[n+1], a1);
            a2 = fmaf(c[n+2], s[n+2], a2);
            a3 = fmaf(c[n+3], s[n+3], a3);
        }
        float e = (a0+a1)+(a2+a3);
        *mp = siluf(fmaf(xv, om, e));
        mp += D_;
    }
}

// ---------------------------------------------------------------------------
// Generic 128x128x16 fp32 GEMM, 256 threads, 8x8 microtile, templated epilogue
//   EPI_STORE : C = acc (+bias[n]) (+add[m,n])
//   EPI_SILU  : C = silu(acc + bias[n] (+add))
//   EPI_RELBIAS: C = acc + bias[2047 + n - m]   (bias := rel_bias)
// batched via blockIdx.z strides.
// ---------------------------------------------------------------------------
constexpr int EPI_STORE=0, EPI_SILU=1, EPI_RELBIAS=2;

template<int EPI, bool HAS_BIAS, bool HAS_ADD>
__global__ void __launch_bounds__(256) gemm_k(
    const float* __restrict__ A, const float* __restrict__ B, float* __restrict__ C,
    int M, int N, int K,
    long batchA, long batchB, long batchC,
    const float* __restrict__ bias,
    const float* __restrict__ add, int add_ld)
{
    __shared__ float As[16][128];
    __shared__ float Bs[16][128];
    A += (long)blockIdx.z * batchA;
    B += (long)blockIdx.z * batchB;
    C += (long)blockIdx.z * batchC;
    const int m0 = blockIdx.y * 128;
    const int n0 = blockIdx.x * 128;
    const int tid = threadIdx.x;
    const int tx = tid & 15, ty = tid >> 4;

    float acc[8][8];
    #pragma unroll
    for(int i=0;i<8;i++)
        #pragma unroll
        for(int j=0;j<8;j++) acc[i][j]=0.f;

    for(int k0=0; k0<K; k0+=16){
        #pragma unroll
        for(int i=0;i<2;i++){
            int idx = tid + i*256;
            int ar = idx >> 2, ac = (idx & 3) << 2;
            float4 av = *reinterpret_cast<const float4*>(A + (long)(m0+ar)*K + k0 + ac);
            As[ac  ][ar]=av.x;
            As[ac+1][ar]=av.y;
            As[ac+2][ar]=av.z;
            As[ac+3][ar]=av.w;
            int br = idx >> 5, bc = (idx & 31) << 2;
            *reinterpret_cast<float4*>(&Bs[br][bc]) =
                *reinterpret_cast<const float4*>(B + (long)(k0+br)*N + n0 + bc);
        }
        __syncthreads();
        #pragma unroll
        for(int k=0;k<16;k++){
            float a[8], bb[8];
            float4 t0=*reinterpret_cast<const float4*>(&As[k][ty*8]);
            float4 t1=*reinterpret_cast<const float4*>(&As[k][ty*8+4]);
            float4 u0=*reinterpret_cast<const float4*>(&Bs[k][tx*8]);
            float4 u1=*reinterpret_cast<const float4*>(&Bs[k][tx*8+4]);
            a[0]=t0.x;a[1]=t0.y;a[2]=t0.z;a[3]=t0.w;a[4]=t1.x;a[5]=t1.y;a[6]=t1.z;a[7]=t1.w;
            bb[0]=u0.x;bb[1]=u0.y;bb[2]=u0.z;bb[3]=u0.w;bb[4]=u1.x;bb[5]=u1.y;bb[6]=u1.z;bb[7]=u1.w;
            #pragma unroll
            for(int i=0;i<8;i++)
                #pragma unroll
                for(int j=0;j<8;j++)
                    acc[i][j] = fmaf(a[i], bb[j], acc[i][j]);
        }
        __syncthreads();
    }

    #pragma unroll
    for(int i=0;i<8;i++){
        int m = m0 + ty*8 + i;
        #pragma unroll
        for(int jj=0;jj<2;jj++){
            float tmp[4];
            #pragma unroll
            for(int j=0;j<4;j++){
                int n = n0 + tx*8 + jj*4 + j;
                float vv = acc[i][jj*4+j];
                if(EPI==EPI_RELBIAS){
                    vv += bias[2047 + n - m];
                } else {
                    if(HAS_BIAS) vv += bias[n];
                    if(HAS_ADD)  vv += add[(long)m*add_ld + n];
                    if(EPI==EPI_SILU) vv = siluf(vv);
                }
                tmp[j]=vv;
            }
            float4 ov; ov.x=tmp[0]; ov.y=tmp[1]; ov.z=tmp[2]; ov.w=tmp[3];
            *reinterpret_cast<float4*>(C + (long)m*N + n0 + tx*8 + jj*4) = ov;
        }
    }
}

// ---------------------------------------------------------------------------
// qh/khT: z = silu(base[:,1024:1152]); qh = (z*g0+b0)/sqrt(Z); khT transposed
// ---------------------------------------------------------------------------
__global__ void qhkh_k(const float* __restrict__ base, const float* __restrict__ gamma,
                       const float* __restrict__ beta, float* __restrict__ qh,
                       float* __restrict__ khT){
    __shared__ float t[32][33];
    int b = blockIdx.z;
    int l0 = blockIdx.x*32, z0 = blockIdx.y*32;
    int tx = threadIdx.x, ty = threadIdx.y;
    int z = z0 + tx;
    float g0=gamma[z], c0=beta[z], g1=gamma[Z_+z], c1=beta[Z_+z];
    #pragma unroll
    for(int i=0;i<4;i++){
        int l = l0 + ty + i*8;
        long row = (long)b*L_ + l;
        float zv = siluf(base[row*MXCOLS + D_ + z]);
        qh[row*Z_ + z] = fmaf(zv, g0, c0) * 0.0883883476483184f;  // Z^-0.5
        t[tx][ty+i*8] = fmaf(zv, g1, c1);
    }
    __syncthreads();
    #pragma unroll
    for(int i=0;i<4;i++){
        int zl = ty + i*8;
        khT[((long)b*Z_ + z0 + zl)*L_ + l0 + tx] = t[zl][tx];
    }
}

// ---------------------------------------------------------------------------
// Row softmax over L=2048 (in place)
// ---------------------------------------------------------------------------
__global__ void softmax_k(float* __restrict__ p){
    long row = blockIdx.x;
    float* pr = p + row*(long)L_;
    int t = threadIdx.x;
    float vals[8];
    float mx = -3.4e38f;
    #pragma unroll
    for(int i=0;i<8;i++){ vals[i]=pr[t+i*256]; mx=fmaxf(mx,vals[i]); }
    #pragma unroll
    for(int off=16;off>0;off>>=1) mx = fmaxf(mx, __shfl_xor_sync(0xffffffffu, mx, off));
    __shared__ float sm[8]; __shared__ float bmx, binv;
    if((t&31)==0) sm[t>>5]=mx;
    __syncthreads();
    if(t==0){ float m2=sm[0]; for(int i=1;i<8;i++) m2=fmaxf(m2,sm[i]); bmx=m2; }
    __syncthreads();
    mx = bmx;
    float s=0.f;
    #pragma unroll
    for(int i=0;i<8;i++){ vals[i]=__expf(vals[i]-mx); s+=vals[i]; }
    #pragma unroll
    for(int off=16;off>0;off>>=1) s += __shfl_xor_sync(0xffffffffu, s, off);
    if((t&31)==0) sm[t>>5]=s;
    __syncthreads();
    if(t==0){ float S=0.f; for(int i=0;i<8;i++) S+=sm[i]; binv=1.f/S; }
    __syncthreads();
    float inv = binv;
    #pragma unroll
    for(int i=0;i<8;i++) pr[t+i*256] = vals[i]*inv;
}

// h *= silu(r), r = base[:,1152:3200]
__global__ void hr_k(float* __restrict__ h, const float* __restrict__ base){
    long i = (long)blockIdx.x*256 + threadIdx.x;
    long row = i >> 11;
    int vc = (int)(i & 2047);
    h[i] *= siluf(base[row*MXCOLS + (D_+Z_) + vc]);
}

// out = x + sigmoid(u)*(h2 - x), u = base[:, :1024]
__global__ void outk(const float* __restrict__ x, const float* __restrict__ base,
                     const float* __restrict__ h2, float* __restrict__ o){
    long i = (long)blockIdx.x*256 + threadIdx.x;
    long row = i >> 10;
    int dc = (int)(i & 1023);
    float u = sigmf(base[row*MXCOLS + dc]);
    float res = x[i];
    o[i] = fmaf(u, h2[i]-res, res);
}

// ---------------------------------------------------------------------------
extern "C" void kernel_launch(void* const* d_in, const int* in_sizes, int n_in,
                              void* d_out, int out_size){
    const float* x       = (const float*)d_in[0];
    const float* n1w     = (const float*)d_in[1];
    const float* n1b     = (const float*)d_in[2];
    const float* e_delta = (const float*)d_in[3];
    const float* e_alpha = (const float*)d_in[4];
    const float* e_beta  = (const float*)d_in[5];
    const float* e_gamma = (const float*)d_in[6];
    const float* e_omega = (const float*)d_in[7];
    const float* vproj_w = (const float*)d_in[8];
    const float* vproj_b = (const float*)d_in[9];
    const float* mx_w    = (const float*)d_in[10];
    const float* mx_b    = (const float*)d_in[11];
    const float* h_w     = (const float*)d_in[12];
    const float* h_b     = (const float*)d_in[13];
    const float* att_g   = (const float*)d_in[14];
    const float* att_b   = (const float*)d_in[15];
    const float* rel_b   = (const float*)d_in[16];
    const float* n2w     = (const float*)d_in[17];
    const float* n2b     = (const float*)d_in[18];
    const float* ff_w1   = (const float*)d_in[19];
    const float* ff_b1   = (const float*)d_in[20];
    const float* ff_w2   = (const float*)d_in[21];
    const float* ff_b2   = (const float*)d_in[22];
    float* outp = (float*)d_out;

    float* S = nullptr;
    cudaGetSymbolAddress((void**)&S, g_scratch);

    float* xn   = S + 0L;
    float* mx   = S + 16777216L;
    float* v    = S + 33554432L;
    float* base = S + 67108864L;
    float* qh   = S + 136314880L;
    float* khT  = S + 138412032L;
    float* qk   = S + 140509184L;
    float* h    = S + 174063616L;
    float* h2   = S + 207618048L;
    float* obuf = S + 224395264L;
    float* yn   = S + 241172480L;
    float* f1   = S + 257949696L;
    float* cc   = S + 291504128L;
    float* qq   = S + 291520512L;

    // norm1
    layernorm_k<<<BLROWS, 256>>>(x, n1w, n1b, xn);
    // EMA branch (scan replaces FFT) -> mx = silu(ema + xn*omega)
    emacoef_k<<<64, 256>>>(e_delta, e_alpha, e_beta, e_gamma, cc, qq);
    emascan_k<<<dim3(D_/256, L_/ECHUNK, B_), 256>>>(xn, cc, qq, e_omega, mx);
    // v = silu(xn @ vproj_w + b)
    gemm_k<EPI_SILU,true,false><<<dim3(V_/128, BLROWS/128, 1), 256>>>(
        xn, vproj_w, v, BLROWS, V_, D_, 0,0,0, vproj_b, nullptr, 0);
    // base = mx @ mx_w + b  (u | z | r | hx packed)
    gemm_k<EPI_STORE,true,false><<<dim3(MXCOLS/128, BLROWS/128, 1), 256>>>(
        mx, mx_w, base, BLROWS, MXCOLS, D_, 0,0,0, mx_b, nullptr, 0);
    // attention
    qhkh_k<<<dim3(L_/32, Z_/32, B_), dim3(32,8)>>>(base, att_g, att_b, qh, khT);
    gemm_k<EPI_RELBIAS,true,false><<<dim3(L_/128, L_/128, B_), 256>>>(
        qh, khT, qk, L_, L_, Z_,
        (long)L_*Z_, (long)Z_*L_, (long)L_*L_, rel_b, nullptr, 0);
    softmax_k<<<BLROWS, 256>>>(qk);
    gemm_k<EPI_STORE,false,false><<<dim3(V_/128, L_/128, B_), 256>>>(
        qk, v, h, L_, V_, L_,
        (long)L_*L_, (long)L_*V_, (long)L_*V_, nullptr, nullptr, 0);
    // h2 = silu(hx + (h*r)@h_w + h_b)
    hr_k<<<BLROWS*(V_/256), 256>>>(h, base);
    gemm_k<EPI_SILU,true,true><<<dim3(D_/128, BLROWS/128, 1), 256>>>(
        h, h_w, h2, BLROWS, D_, V_, 0,0,0, h_b, base + (D_+Z_+V_), MXCOLS);
    // out = x + u*(h2 - x)
    outk<<<BLROWS*(D_/256), 256>>>(x, base, h2, obuf);
    // FFN: final = out + (silu(ln2(out)@ff_w1+b1))@ff_w2 + b2
    layernorm_k<<<BLROWS, 256>>>(obuf, n2w, n2b, yn);
    gemm_k<EPI_SILU,true,false><<<dim3((2*D_)/128, BLROWS/128, 1), 256>>>(
        yn, ff_w1, f1, BLROWS, 2*D_, D_, 0,0,0, ff_b1, nullptr, 0);
    gemm_k<EPI_STORE,true,true><<<dim3(D_/128, BLROWS/128, 1), 256>>>(
        f1, ff_w2, outp, BLROWS, D_, 2*D_, 0,0,0, ff_b2, obuf, D_);
}

// round 13
// speedup vs baseline: 1.0015x; 1.0015x over previous
#include <cuda_runtime.h>

#define B_ 8
#define L_ 2048
#define D_ 1024
#define Z_ 128
#define V_ 2048
#define NEMA 16
#define BLROWS (B_*L_)            /* 16384 */
#define MXCOLS (Z_ + V_ + 2*D_)   /* 4224  */
#define ECHUNK 256

// ---------------------------------------------------------------------------
// Scratch (static device allocation; no cudaMalloc allowed)
// layout (float offsets):
//   xn    @ 0          16777216   (BL*D)
//   mx    @ 16777216   16777216
//   v     @ 33554432   33554432   (BL*V)
//   base  @ 67108864   69206016   (BL*4224)
//   qh    @ 136314880  2097152    (B*L*Z)
//   khT   @ 138412032  2097152
//   qk    @ 140509184  33554432   (B*L*L)
//   h     @ 174063616  33554432
//   h2    @ 207618048  16777216
//   out   @ 224395264  16777216
//   yn    @ 241172480  16777216
//   f1    @ 257949696  33554432
//   c     @ 291504128  16384
//   q     @ 291520512  16384
// ---------------------------------------------------------------------------
__device__ float g_scratch[291536896];

__device__ __forceinline__ float siluf(float x){ return x / (1.f + __expf(-x)); }
__device__ __forceinline__ float sigmf(float x){ return 1.f / (1.f + __expf(-x)); }

// ---------------------------------------------------------------------------
// LayerNorm over D=1024; one block per row, 256 threads * float4
// ---------------------------------------------------------------------------
__global__ void layernorm_k(const float* __restrict__ x, const float* __restrict__ w,
                            const float* __restrict__ b, float* __restrict__ o){
    long row = blockIdx.x;
    int t = threadIdx.x;
    float4 xv = reinterpret_cast<const float4*>(x + row*D_)[t];
    float s  = xv.x+xv.y+xv.z+xv.w;
    float s2 = xv.x*xv.x+xv.y*xv.y+xv.z*xv.z+xv.w*xv.w;
    #pragma unroll
    for(int off=16; off>0; off>>=1){
        s  += __shfl_xor_sync(0xffffffffu, s,  off);
        s2 += __shfl_xor_sync(0xffffffffu, s2, off);
    }
    __shared__ float ss[8], ss2[8];
    __shared__ float smu, sinv;
    if((t&31)==0){ ss[t>>5]=s; ss2[t>>5]=s2; }
    __syncthreads();
    if(t==0){
        float S=0.f, S2=0.f;
        #pragma unroll
        for(int i=0;i<8;i++){ S+=ss[i]; S2+=ss2[i]; }
        float mu  = S*(1.f/D_);
        float var = S2*(1.f/D_) - mu*mu;
        smu = mu; sinv = rsqrtf(var + 1e-5f);
    }
    __syncthreads();
    float mu = smu, inv = sinv;
    float4 wv = reinterpret_cast<const float4*>(w)[t];
    float4 bv = reinterpret_cast<const float4*>(b)[t];
    float4 ov;
    ov.x = (xv.x-mu)*inv*wv.x + bv.x;
    ov.y = (xv.y-mu)*inv*wv.y + bv.y;
    ov.z = (xv.z-mu)*inv*wv.z + bv.z;
    ov.w = (xv.w-mu)*inv*wv.w + bv.w;
    reinterpret_cast<float4*>(o + row*D_)[t] = ov;
}

// ---------------------------------------------------------------------------
// EMA coefficients: c = p*beta*gamma/sqrt(N), q = 1 - p*sigmoid(alpha)
// ---------------------------------------------------------------------------
__global__ void emacoef_k(const float* __restrict__ delta, const float* __restrict__ alpha,
                          const float* __restrict__ beta,  const float* __restrict__ gamma,
                          float* __restrict__ c, float* __restrict__ q){
    int i = blockIdx.x*256 + threadIdx.x;   // D*N = 16384
    float p = sigmf(delta[i]);
    q[i] = 1.f - p*sigmf(alpha[i]);
    c[i] = p*beta[i]*gamma[i]*0.25f;        // 1/sqrt(16)
}

// ---------------------------------------------------------------------------
// EMA scan (replaces the FFT conv) fused with mx = silu(ema + xn*omega).
// Chunked: each thread owns (b,d,chunk); 256-step warm-up re-establishes the
// state (truncation <= q^256 <= 1e-11 for this data).
// ---------------------------------------------------------------------------
__global__ void emascan_k(const float* __restrict__ xn, const float* __restrict__ cArr,
                          const float* __restrict__ qArr, const float* __restrict__ omega,
                          float* __restrict__ mx){
    int d = blockIdx.x*256 + threadIdx.x;
    int chunk = blockIdx.y;
    int b = blockIdx.z;
    float c[NEMA], q[NEMA], s[NEMA];
    #pragma unroll
    for(int n=0;n<NEMA;n++){ c[n]=cArr[d*NEMA+n]; q[n]=qArr[d*NEMA+n]; s[n]=0.f; }
    float om = omega[d];
    int start = chunk*ECHUNK;
    int l0 = start - ECHUNK; if(l0 < 0) l0 = 0;
    const float* xp = xn + ((long)b*L_ + l0)*D_ + d;
    for(int l=l0; l<start; l++){
        float xv = *xp; xp += D_;
        #pragma unroll
        for(int n=0;n<NEMA;n++) s[n] = fmaf(q[n], s[n], xv);
    }
    float* mp = mx + ((long)b*L_ + start)*D_ + d;
    for(int l=0; l<ECHUNK; l++){
        float xv = *xp; xp += D_;
        float a0=0.f,a1=0.f,a2=0.f,a3=0.f;
        #pragma unroll
        for(int n=0;n<NEMA;n+=4){
            s[n]   = fmaf(q[n],   s[n],   xv);
            s[n+1] = fmaf(q[n+1], s[n+1], xv);
            s[n+2] = fmaf(q[n+2], s[n+2], xv);
            s[n+3] = fmaf(q[n+3], s[n+3], xv);
            a0 = fmaf(c[n],   s[n],   a0);
            a1 = fmaf(c[n+1], s[n+1], a1);
            a2 = fmaf(c[n+2], s[n+2], a2);
            a3 = fmaf(c[n+3], s[n+3], a3);
        }
        float e = (a0+a1)+(a2+a3);
        *mp = siluf(fmaf(xv, om, e));
        mp += D_;
    }
}

// ---------------------------------------------------------------------------
// Generic 128x128x16 fp32 GEMM, 256 threads, 8x8 microtile, templated epilogue
//   EPI_STORE : C = acc (+bias[n]) (+add[m,n])
//   EPI_SILU  : C = silu(acc + bias[n] (+add))
//   EPI_RELBIAS: C = acc + bias[2047 + n - m]   (bias := rel_bias)
// batched via blockIdx.z strides.
// ---------------------------------------------------------------------------
constexpr int EPI_STORE=0, EPI_SILU=1, EPI_RELBIAS=2;

template<int EPI, bool HAS_BIAS, bool HAS_ADD>
__global__ void __launch_bounds__(256) gemm_k(
    const float* __restrict__ A, const float* __restrict__ B, float* __restrict__ C,
    int M, int N, int K,
    long batchA, long batchB, long batchC,
    const float* __restrict__ bias,
    const float* __restrict__ add, int add_ld)
{
    __shared__ float As[16][128];
    __shared__ float Bs[16][128];
    A += (long)blockIdx.z * batchA;
    B += (long)blockIdx.z * batchB;
    C += (long)blockIdx.z * batchC;
    const int m0 = blockIdx.y * 128;
    const int n0 = blockIdx.x * 128;
    const int tid = threadIdx.x;
    const int tx = tid & 15, ty = tid >> 4;

    float acc[8][8];
    #pragma unroll
    for(int i=0;i<8;i++)
        #pragma unroll
        for(int j=0;j<8;j++) acc[i][j]=0.f;

    for(int k0=0; k0<K; k0+=16){
        #pragma unroll
        for(int i=0;i<2;i++){
            int idx = tid + i*256;
            int ar = idx >> 2, ac = (idx & 3) << 2;
            float4 av = *reinterpret_cast<const float4*>(A + (long)(m0+ar)*K + k0 + ac);
            As[ac  ][ar]=av.x;
            As[ac+1][ar]=av.y;
            As[ac+2][ar]=av.z;
            As[ac+3][ar]=av.w;
            int br = idx >> 5, bc = (idx & 31) << 2;
            *reinterpret_cast<float4*>(&Bs[br][bc]) =
                *reinterpret_cast<const float4*>(B + (long)(k0+br)*N + n0 + bc);
        }
        __syncthreads();
        #pragma unroll
        for(int k=0;k<16;k++){
            float a[8], bb[8];
            float4 t0=*reinterpret_cast<const float4*>(&As[k][ty*8]);
            float4 t1=*reinterpret_cast<const float4*>(&As[k][ty*8+4]);
            float4 u0=*reinterpret_cast<const float4*>(&Bs[k][tx*8]);
            float4 u1=*reinterpret_cast<const float4*>(&Bs[k][tx*8+4]);
            a[0]=t0.x;a[1]=t0.y;a[2]=t0.z;a[3]=t0.w;a[4]=t1.x;a[5]=t1.y;a[6]=t1.z;a[7]=t1.w;
            bb[0]=u0.x;bb[1]=u0.y;bb[2]=u0.z;bb[3]=u0.w;bb[4]=u1.x;bb[5]=u1.y;bb[6]=u1.z;bb[7]=u1.w;
            #pragma unroll
            for(int i=0;i<8;i++)
                #pragma unroll
                for(int j=0;j<8;j++)
                    acc[i][j] = fmaf(a[i], bb[j], acc[i][j]);
        }
        __syncthreads();
    }

    #pragma unroll
    for(int i=0;i<8;i++){
        int m = m0 + ty*8 + i;
        #pragma unroll
        for(int jj=0;jj<2;jj++){
            float tmp[4];
            #pragma unroll
            for(int j=0;j<4;j++){
                int n = n0 + tx*8 + jj*4 + j;
                float vv = acc[i][jj*4+j];
                if(EPI==EPI_RELBIAS){
                    vv += bias[2047 + n - m];
                } else {
                    if(HAS_BIAS) vv += bias[n];
                    if(HAS_ADD)  vv += add[(long)m*add_ld + n];
                    if(EPI==EPI_SILU) vv = siluf(vv);
                }
                tmp[j]=vv;
            }
            float4 ov; ov.x=tmp[0]; ov.y=tmp[1]; ov.z=tmp[2]; ov.w=tmp[3];
            *reinterpret_cast<float4*>(C + (long)m*N + n0 + tx*8 + jj*4) = ov;
        }
    }
}

// ---------------------------------------------------------------------------
// qh/khT: z = silu(base[:,1024:1152]); qh = (z*g0+b0)/sqrt(Z); khT transposed
// ---------------------------------------------------------------------------
__global__ void qhkh_k(const float* __restrict__ base, const float* __restrict__ gamma,
                       const float* __restrict__ beta, float* __restrict__ qh,
                       float* __restrict__ khT){
    __shared__ float t[32][33];
    int b = blockIdx.z;
    int l0 = blockIdx.x*32, z0 = blockIdx.y*32;
    int tx = threadIdx.x, ty = threadIdx.y;
    int z = z0 + tx;
    float g0=gamma[z], c0=beta[z], g1=gamma[Z_+z], c1=beta[Z_+z];
    #pragma unroll
    for(int i=0;i<4;i++){
        int l = l0 + ty + i*8;
        long row = (long)b*L_ + l;
        float zv = siluf(base[row*MXCOLS + D_ + z]);
        qh[row*Z_ + z] = fmaf(zv, g0, c0) * 0.0883883476483184f;  // Z^-0.5
        t[tx][ty+i*8] = fmaf(zv, g1, c1);
    }
    __syncthreads();
    #pragma unroll
    for(int i=0;i<4;i++){
        int zl = ty + i*8;
        khT[((long)b*Z_ + z0 + zl)*L_ + l0 + tx] = t[zl][tx];
    }
}

// ---------------------------------------------------------------------------
// Row softmax over L=2048 (in place)
// ---------------------------------------------------------------------------
__global__ void softmax_k(float* __restrict__ p){
    long row = blockIdx.x;
    float* pr = p + row*(long)L_;
    int t = threadIdx.x;
    float vals[8];
    float mx = -3.4e38f;
    #pragma unroll
    for(int i=0;i<8;i++){ vals[i]=pr[t+i*256]; mx=fmaxf(mx,vals[i]); }
    #pragma unroll
    for(int off=16;off>0;off>>=1) mx = fmaxf(mx, __shfl_xor_sync(0xffffffffu, mx, off));
    __shared__ float sm[8]; __shared__ float bmx, binv;
    if((t&31)==0) sm[t>>5]=mx;
    __syncthreads();
    if(t==0){ float m2=sm[0]; for(int i=1;i<8;i++) m2=fmaxf(m2,sm[i]); bmx=m2; }
    __syncthreads();
    mx = bmx;
    float s=0.f;
    #pragma unroll
    for(int i=0;i<8;i++){ vals[i]=__expf(vals[i]-mx); s+=vals[i]; }
    #pragma unroll
    for(int off=16;off>0;off>>=1) s += __shfl_xor_sync(0xffffffffu, s, off);
    if((t&31)==0) sm[t>>5]=s;
    __syncthreads();
    if(t==0){ float S=0.f; for(int i=0;i<8;i++) S+=sm[i]; binv=1.f/S; }
    __syncthreads();
    float inv = binv;
    #pragma unroll
    for(int i=0;i<8;i++) pr[t+i*256] = vals[i]*inv;
}

// h *= silu(r), r = base[:,1152:3200]
__global__ void hr_k(float* __restrict__ h, const float* __restrict__ base){
    long i = (long)blockIdx.x*256 + threadIdx.x;
    long row = i >> 11;
    int vc = (int)(i & 2047);
    h[i] *= siluf(base[row*MXCOLS + (D_+Z_) + vc]);
}

// out = x + sigmoid(u)*(h2 - x), u = base[:, :1024]
__global__ void outk(const float* __restrict__ x, const float* __restrict__ base,
                     const float* __restrict__ h2, float* __restrict__ o){
    long i = (long)blockIdx.x*256 + threadIdx.x;
    long row = i >> 10;
    int dc = (int)(i & 1023);
    float u = sigmf(base[row*MXCOLS + dc]);
    float res = x[i];
    o[i] = fmaf(u, h2[i]-res, res);
}

// ---------------------------------------------------------------------------
extern "C" void kernel_launch(void* const* d_in, const int* in_sizes, int n_in,
                              void* d_out, int out_size){
    const float* x       = (const float*)d_in[0];
    const float* n1w     = (const float*)d_in[1];
    const float* n1b     = (const float*)d_in[2];
    const float* e_delta = (const float*)d_in[3];
    const float* e_alpha = (const float*)d_in[4];
    const float* e_beta  = (const float*)d_in[5];
    const float* e_gamma = (const float*)d_in[6];
    const float* e_omega = (const float*)d_in[7];
    const float* vproj_w = (const float*)d_in[8];
    const float* vproj_b = (const float*)d_in[9];
    const float* mx_w    = (const float*)d_in[10];
    const float* mx_b    = (const float*)d_in[11];
    const float* h_w     = (const float*)d_in[12];
    const float* h_b     = (const float*)d_in[13];
    const float* att_g   = (const float*)d_in[14];
    const float* att_b   = (const float*)d_in[15];
    const float* rel_b   = (const float*)d_in[16];
    const float* n2w     = (const float*)d_in[17];
    const float* n2b     = (const float*)d_in[18];
    const float* ff_w1   = (const float*)d_in[19];
    const float* ff_b1   = (const float*)d_in[20];
    const float* ff_w2   = (const float*)d_in[21];
    const float* ff_b2   = (const float*)d_in[22];
    float* outp = (float*)d_out;

    float* S = nullptr;
    cudaGetSymbolAddress((void**)&S, g_scratch);

    float* xn   = S + 0L;
    float* mx   = S + 16777216L;
    float* v    = S + 33554432L;
    float* base = S + 67108864L;
    float* qh   = S + 136314880L;
    float* khT  = S + 138412032L;
    float* qk   = S + 140509184L;
    float* h    = S + 174063616L;
    float* h2   = S + 207618048L;
    float* obuf = S + 224395264L;
    float* yn   = S + 241172480L;
    float* f1   = S + 257949696L;
    float* cc   = S + 291504128L;
    float* qq   = S + 291520512L;

    // norm1
    layernorm_k<<<BLROWS, 256>>>(x, n1w, n1b, xn);
    // EMA branch (scan replaces FFT) -> mx = silu(ema + xn*omega)
    emacoef_k<<<64, 256>>>(e_delta, e_alpha, e_beta, e_gamma, cc, qq);
    emascan_k<<<dim3(D_/256, L_/ECHUNK, B_), 256>>>(xn, cc, qq, e_omega, mx);
    // v = silu(xn @ vproj_w + b)
    gemm_k<EPI_SILU,true,false><<<dim3(V_/128, BLROWS/128, 1), 256>>>(
        xn, vproj_w, v, BLROWS, V_, D_, 0,0,0, vproj_b, nullptr, 0);
    // base = mx @ mx_w + b  (u | z | r | hx packed)
    gemm_k<EPI_STORE,true,false><<<dim3(MXCOLS/128, BLROWS/128, 1), 256>>>(
        mx, mx_w, base, BLROWS, MXCOLS, D_, 0,0,0, mx_b, nullptr, 0);
    // attention
    qhkh_k<<<dim3(L_/32, Z_/32, B_), dim3(32,8)>>>(base, att_g, att_b, qh, khT);
    gemm_k<EPI_RELBIAS,true,false><<<dim3(L_/128, L_/128, B_), 256>>>(
        qh, khT, qk, L_, L_, Z_,
        (long)L_*Z_, (long)Z_*L_, (long)L_*L_, rel_b, nullptr, 0);
    softmax_k<<<BLROWS, 256>>>(qk);
    gemm_k<EPI_STORE,false,false><<<dim3(V_/128, L_/128, B_), 256>>>(
        qk, v, h, L_, V_, L_,
        (long)L_*L_, (long)L_*V_, (long)L_*V_, nullptr, nullptr, 0);
    // h2 = silu(hx + (h*r)@h_w + h_b)
    hr_k<<<BLROWS*(V_/256), 256>>>(h, base);
    gemm_k<EPI_SILU,true,true><<<dim3(D_/128, BLROWS/128, 1), 256>>>(
        h, h_w, h2, BLROWS, D_, V_, 0,0,0, h_b, base + (D_+Z_+V_), MXCOLS);
    // out = x + u*(h2 - x)
    outk<<<BLROWS*(D_/256), 256>>>(x, base, h2, obuf);
    // FFN: final = out + (silu(ln2(out)@ff_w1+b1))@ff_w2 + b2
    layernorm_k<<<BLROWS, 256>>>(obuf, n2w, n2b, yn);
    gemm_k<EPI_SILU,true,false><<<dim3((2*D_)/128, BLROWS/128, 1), 256>>>(
        yn, ff_w1, f1, BLROWS, 2*D_, D_, 0,0,0, ff_b1, nullptr, 0);
    gemm_k<EPI_STORE,true,true><<<dim3(D_/128, BLROWS/128, 1), 256>>>(
        f1, ff_w2, outp, BLROWS, D_, 2*D_, 0,0,0, ff_b2, obuf, D_);
}

// round 15
// speedup vs baseline: 2.6676x; 2.6634x over previous
#include <cuda_runtime.h>
#include <cstdint>

#define B_ 8
#define L_ 2048
#define D_ 1024
#define Z_ 128
#define V_ 2048
#define NEMA 16
#define BLROWS (B_*L_)            /* 16384 */
#define MXCOLS (Z_ + V_ + 2*D_)   /* 4224  */
#define ECHUNK 256

// ---------------------------------------------------------------------------
// Scratch (static device allocation; no cudaMalloc allowed)
// ---------------------------------------------------------------------------
__device__ float g_scratch[337805312];

__device__ __forceinline__ float siluf(float x){ return x / (1.f + __expf(-x)); }
__device__ __forceinline__ float sigmf(float x){ return 1.f / (1.f + __expf(-x)); }
__device__ __forceinline__ uint32_t f2tf32(float x){
    uint32_t u; asm("cvt.rna.tf32.f32 %0, %1;" : "=r"(u) : "f"(x)); return u;
}

// ---------------------------------------------------------------------------
// LayerNorm over D=1024; one block per row, 256 threads * float4
// ---------------------------------------------------------------------------
__global__ void layernorm_k(const float* __restrict__ x, const float* __restrict__ w,
                            const float* __restrict__ b, float* __restrict__ o){
    long row = blockIdx.x;
    int t = threadIdx.x;
    float4 xv = reinterpret_cast<const float4*>(x + row*D_)[t];
    float s  = xv.x+xv.y+xv.z+xv.w;
    float s2 = xv.x*xv.x+xv.y*xv.y+xv.z*xv.z+xv.w*xv.w;
    #pragma unroll
    for(int off=16; off>0; off>>=1){
        s  += __shfl_xor_sync(0xffffffffu, s,  off);
        s2 += __shfl_xor_sync(0xffffffffu, s2, off);
    }
    __shared__ float ss[8], ss2[8];
    __shared__ float smu, sinv;
    if((t&31)==0){ ss[t>>5]=s; ss2[t>>5]=s2; }
    __syncthreads();
    if(t==0){
        float S=0.f, S2=0.f;
        #pragma unroll
        for(int i=0;i<8;i++){ S+=ss[i]; S2+=ss2[i]; }
        float mu  = S*(1.f/D_);
        float var = S2*(1.f/D_) - mu*mu;
        smu = mu; sinv = rsqrtf(var + 1e-5f);
    }
    __syncthreads();
    float mu = smu, inv = sinv;
    float4 wv = reinterpret_cast<const float4*>(w)[t];
    float4 bv = reinterpret_cast<const float4*>(b)[t];
    float4 ov;
    ov.x = (xv.x-mu)*inv*wv.x + bv.x;
    ov.y = (xv.y-mu)*inv*wv.y + bv.y;
    ov.z = (xv.z-mu)*inv*wv.z + bv.z;
    ov.w = (xv.w-mu)*inv*wv.w + bv.w;
    reinterpret_cast<float4*>(o + row*D_)[t] = ov;
}

// ---------------------------------------------------------------------------
__global__ void emacoef_k(const float* __restrict__ delta, const float* __restrict__ alpha,
                          const float* __restrict__ beta,  const float* __restrict__ gamma,
                          float* __restrict__ c, float* __restrict__ q){
    int i = blockIdx.x*256 + threadIdx.x;   // D*N = 16384
    float p = sigmf(delta[i]);
    q[i] = 1.f - p*sigmf(alpha[i]);
    c[i] = p*beta[i]*gamma[i]*0.25f;        // 1/sqrt(16)
}

// ---------------------------------------------------------------------------
// EMA scan fused with mx = silu(ema + xn*omega). Chunked with 256-step warm-up.
// ---------------------------------------------------------------------------
__global__ void emascan_k(const float* __restrict__ xn, const float* __restrict__ cArr,
                          const float* __restrict__ qArr, const float* __restrict__ omega,
                          float* __restrict__ mx){
    int d = blockIdx.x*256 + threadIdx.x;
    int chunk = blockIdx.y;
    int b = blockIdx.z;
    float c[NEMA], q[NEMA], s[NEMA];
    #pragma unroll
    for(int n=0;n<NEMA;n++){ c[n]=cArr[d*NEMA+n]; q[n]=qArr[d*NEMA+n]; s[n]=0.f; }
    float om = omega[d];
    int start = chunk*ECHUNK;
    int l0 = start - ECHUNK; if(l0 < 0) l0 = 0;
    const float* xp = xn + ((long)b*L_ + l0)*D_ + d;
    for(int l=l0; l<start; l++){
        float xv = *xp; xp += D_;
        #pragma unroll
        for(int n=0;n<NEMA;n++) s[n] = fmaf(q[n], s[n], xv);
    }
    float* mp = mx + ((long)b*L_ + start)*D_ + d;
    for(int l=0; l<ECHUNK; l++){
        float xv = *xp; xp += D_;
        float a0=0.f,a1=0.f,a2=0.f,a3=0.f;
        #pragma unroll
        for(int n=0;n<NEMA;n+=4){
            s[n]   = fmaf(q[n],   s[n],   xv);
            s[n+1] = fmaf(q[n+1], s[n+1], xv);
            s[n+2] = fmaf(q[n+2], s[n+2], xv);
            s[n+3] = fmaf(q[n+3], s[n+3], xv);
            a0 = fmaf(c[n],   s[n],   a0);
            a1 = fmaf(c[n+1], s[n+1], a1);
            a2 = fmaf(c[n+2], s[n+2], a2);
            a3 = fmaf(c[n+3], s[n+3], a3);
        }
        float e = (a0+a1)+(a2+a3);
        *mp = siluf(fmaf(xv, om, e));
        mp += D_;
    }
}

// ---------------------------------------------------------------------------
// Generic 32x32-tiled transpose: dst[c][r] = src[r][c], batched by blockIdx.z
// ---------------------------------------------------------------------------
__global__ void transpose_k(const float* __restrict__ src, float* __restrict__ dst,
                            int R, int C, long sb, long db){
    __shared__ float t[32][33];
    src += (long)blockIdx.z * sb;
    dst += (long)blockIdx.z * db;
    int r0 = blockIdx.y*32, c0 = blockIdx.x*32;
    int tx = threadIdx.x, ty = threadIdx.y;
    #pragma unroll
    for(int i=0;i<4;i++)
        t[ty+i*8][tx] = src[(long)(r0+ty+i*8)*C + c0 + tx];
    __syncthreads();
    #pragma unroll
    for(int i=0;i<4;i++)
        dst[(long)(c0+ty+i*8)*R + r0 + tx] = t[tx][ty+i*8];
}

// ---------------------------------------------------------------------------
// tf32 tensor-core GEMM via mma.sync.m16n8k8 (base-target safe, no tcgen05).
// CTA tile 128x128, KTILE 32, 8 warps (4M x 2N), warp tile 32x64.
// Smem crosswise layout off = k4*512 + (r+k4)*4 + (k&3):
//   - every fragment LDS address == const + lane  -> conflict-free
//   - staging st.v4 banks rotate by 4 per k4      -> conflict-free
// A row-major [M,K]; B passed K-major transposed [N,K]. Batched via blockIdx.z.
// ---------------------------------------------------------------------------
constexpr int EPI_STORE=0, EPI_SILU=1, EPI_RELBIAS=2;

template<int EPI, bool HAS_BIAS, bool HAS_ADD>
__global__ void __launch_bounds__(256,2) gemm_mma(
    const float* __restrict__ A, const float* __restrict__ Bt, float* __restrict__ C,
    int M, int N, int K, long bA, long bB, long bC,
    const float* __restrict__ bias,
    const float* __restrict__ add, int add_ld)
{
    __shared__ float As[4224];
    __shared__ float Bs[4224];
    A  += (long)blockIdx.z * bA;
    Bt += (long)blockIdx.z * bB;
    C  += (long)blockIdx.z * bC;
    const int m0 = blockIdx.y*128, n0 = blockIdx.x*128;
    const int tid = threadIdx.x, lane = tid & 31, wid = tid >> 5;
    const int wM = (wid & 3)*32, wN = (wid >> 2)*64;

    float acc[2][8][4];
    #pragma unroll
    for(int i=0;i<2;i++)
        #pragma unroll
        for(int j=0;j<8;j++)
            #pragma unroll
            for(int k=0;k<4;k++) acc[i][j][k]=0.f;

    const float* Ap = A  + (long)m0*K;
    const float* Bp = Bt + (long)n0*K;

    for (int k0 = 0; k0 < K; k0 += 32){
        // stage 128x32 of A and B (tf32-rounded) into crosswise smem
        #pragma unroll
        for (int i = 0; i < 4; i++){
            int idx = tid + i*256;            // 0..1023
            int r = idx >> 3, c4 = idx & 7;
            int o = c4*512 + (r + c4)*4;
            float4 av = *reinterpret_cast<const float4*>(Ap + (long)r*K + k0 + c4*4);
            float4 sv;
            sv.x = __uint_as_float(f2tf32(av.x));
            sv.y = __uint_as_float(f2tf32(av.y));
            sv.z = __uint_as_float(f2tf32(av.z));
            sv.w = __uint_as_float(f2tf32(av.w));
            *reinterpret_cast<float4*>(&As[o]) = sv;
            float4 bv = *reinterpret_cast<const float4*>(Bp + (long)r*K + k0 + c4*4);
            sv.x = __uint_as_float(f2tf32(bv.x));
            sv.y = __uint_as_float(f2tf32(bv.y));
            sv.z = __uint_as_float(f2tf32(bv.z));
            sv.w = __uint_as_float(f2tf32(bv.w));
            *reinterpret_cast<float4*>(&Bs[o]) = sv;
        }
        __syncthreads();
        #pragma unroll
        for (int k8 = 0; k8 < 4; k8++){
            uint32_t af[2][4];
            #pragma unroll
            for (int mt = 0; mt < 2; mt++){
                int m = wM + mt*16 + (lane >> 2);
                int o = k8*1024 + (m + 2*k8)*4 + (lane & 3);
                af[mt][0] = __float_as_uint(As[o]);        // (r,   c)
                af[mt][1] = __float_as_uint(As[o+32]);     // (r+8, c)
                af[mt][2] = __float_as_uint(As[o+516]);    // (r,   c+4)
                af[mt][3] = __float_as_uint(As[o+548]);    // (r+8, c+4)
            }
            #pragma unroll
            for (int nt = 0; nt < 8; nt++){
                int n = wN + nt*8 + (lane >> 2);
                int o = k8*1024 + (n + 2*k8)*4 + (lane & 3);
                uint32_t bf0 = __float_as_uint(Bs[o]);     // (k,   n)
                uint32_t bf1 = __float_as_uint(Bs[o+516]); // (k+4, n)
                #pragma unroll
                for (int mt = 0; mt < 2; mt++){
                    asm volatile(
                        "mma.sync.aligned.m16n8k8.row.col.f32.tf32.tf32.f32 "
                        "{%0,%1,%2,%3}, {%4,%5,%6,%7}, {%8,%9}, {%0,%1,%2,%3};"
                        : "+f"(acc[mt][nt][0]), "+f"(acc[mt][nt][1]),
                          "+f"(acc[mt][nt][2]), "+f"(acc[mt][nt][3])
                        : "r"(af[mt][0]), "r"(af[mt][1]), "r"(af[mt][2]), "r"(af[mt][3]),
                          "r"(bf0), "r"(bf1));
                }
            }
        }
        __syncthreads();
    }

    // Epilogue: fused bias/silu/relbias/add, direct float2 stores
    #pragma unroll
    for (int mt = 0; mt < 2; mt++){
        #pragma unroll
        for (int rh = 0; rh < 2; rh++){
            int m = m0 + wM + mt*16 + (lane >> 2) + rh*8;
            #pragma unroll
            for (int nt = 0; nt < 8; nt++){
                int n = n0 + wN + nt*8 + (lane & 3)*2;
                float v0 = acc[mt][nt][rh*2+0];
                float v1 = acc[mt][nt][rh*2+1];
                if (EPI == EPI_RELBIAS){
                    v0 += bias[2047 + n - m];
                    v1 += bias[2048 + n - m];
                } else {
                    if (HAS_BIAS){ v0 += bias[n]; v1 += bias[n+1]; }
                    if (HAS_ADD){
                        v0 += add[(long)m*add_ld + n];
                        v1 += add[(long)m*add_ld + n + 1];
                    }
                    if (EPI == EPI_SILU){ v0 = siluf(v0); v1 = siluf(v1); }
                }
                float2 ov; ov.x = v0; ov.y = v1;
                *reinterpret_cast<float2*>(C + (long)m*N + n) = ov;
            }
        }
    }
}

// ---------------------------------------------------------------------------
// qh/kh: z = silu(base[:,1024:1152]); qh = (z*g0+b0)/sqrt(Z); kh = z*g1+b1
// ---------------------------------------------------------------------------
__global__ void qhkh_k(const float* __restrict__ base, const float* __restrict__ g,
                       const float* __restrict__ be, float* __restrict__ qh,
                       float* __restrict__ kh){
    long i = (long)blockIdx.x*256 + threadIdx.x;   // BL*Z
    long row = i >> 7;
    int z = (int)(i & 127);
    float zv = siluf(base[row*MXCOLS + D_ + z]);
    qh[i] = fmaf(zv, g[z], be[z]) * 0.0883883476483184f;  // Z^-0.5
    kh[i] = fmaf(zv, g[Z_+z], be[Z_+z]);
}

// ---------------------------------------------------------------------------
// Row softmax over L=2048 (in place)
// ---------------------------------------------------------------------------
__global__ void softmax_k(float* __restrict__ p){
    long row = blockIdx.x;
    float* pr = p + row*(long)L_;
    int t = threadIdx.x;
    float vals[8];
    float mx = -3.4e38f;
    #pragma unroll
    for(int i=0;i<8;i++){ vals[i]=pr[t+i*256]; mx=fmaxf(mx,vals[i]); }
    #pragma unroll
    for(int off=16;off>0;off>>=1) mx = fmaxf(mx, __shfl_xor_sync(0xffffffffu, mx, off));
    __shared__ float smr[8]; __shared__ float bmx, binv;
    if((t&31)==0) smr[t>>5]=mx;
    __syncthreads();
    if(t==0){ float m2=smr[0]; for(int i=1;i<8;i++) m2=fmaxf(m2,smr[i]); bmx=m2; }
    __syncthreads();
    mx = bmx;
    float s=0.f;
    #pragma unroll
    for(int i=0;i<8;i++){ vals[i]=__expf(vals[i]-mx); s+=vals[i]; }
    #pragma unroll
    for(int off=16;off>0;off>>=1) s += __shfl_xor_sync(0xffffffffu, s, off);
    if((t&31)==0) smr[t>>5]=s;
    __syncthreads();
    if(t==0){ float S=0.f; for(int i=0;i<8;i++) S+=smr[i]; binv=1.f/S; }
    __syncthreads();
    float inv = binv;
    #pragma unroll
    for(int i=0;i<8;i++) pr[t+i*256] = vals[i]*inv;
}

// h *= silu(r), r = base[:,1152:3200]
__global__ void hr_k(float* __restrict__ h, const float* __restrict__ base){
    long i = (long)blockIdx.x*256 + threadIdx.x;
    long row = i >> 11;
    int vc = (int)(i & 2047);
    h[i] *= siluf(base[row*MXCOLS + (D_+Z_) + vc]);
}

// out = x + sigmoid(u)*(h2 - x), u = base[:, :1024]
__global__ void outk(const float* __restrict__ x, const float* __restrict__ base,
                     const float* __restrict__ h2, float* __restrict__ o){
    long i = (long)blockIdx.x*256 + threadIdx.x;
    long row = i >> 10;
    int dc = (int)(i & 1023);
    float u = sigmf(base[row*MXCOLS + dc]);
    float res = x[i];
    o[i] = fmaf(u, h2[i]-res, res);
}

// ---------------------------------------------------------------------------
extern "C" void kernel_launch(void* const* d_in, const int* in_sizes, int n_in,
                              void* d_out, int out_size){
    const float* x       = (const float*)d_in[0];
    const float* n1w     = (const float*)d_in[1];
    const float* n1b     = (const float*)d_in[2];
    const float* e_delta = (const float*)d_in[3];
    const float* e_alpha = (const float*)d_in[4];
    const float* e_beta  = (const float*)d_in[5];
    const float* e_gamma = (const float*)d_in[6];
    const float* e_omega = (const float*)d_in[7];
    const float* vproj_w = (const float*)d_in[8];
    const float* vproj_b = (const float*)d_in[9];
    const float* mx_w    = (const float*)d_in[10];
    const float* mx_b    = (const float*)d_in[11];
    const float* h_w     = (const float*)d_in[12];
    const float* h_b     = (const float*)d_in[13];
    const float* att_g   = (const float*)d_in[14];
    const float* att_b   = (const float*)d_in[15];
    const float* rel_b   = (const float*)d_in[16];
    const float* n2w     = (const float*)d_in[17];
    const float* n2b     = (const float*)d_in[18];
    const float* ff_w1   = (const float*)d_in[19];
    const float* ff_b1   = (const float*)d_in[20];
    const float* ff_w2   = (const float*)d_in[21];
    const float* ff_b2   = (const float*)d_in[22];
    float* outp = (float*)d_out;

    float* S = nullptr;
    cudaGetSymbolAddress((void**)&S, g_scratch);

    float* xn   = S + 0L;
    float* mx   = S + 16777216L;
    float* v    = S + 33554432L;
    float* base = S + 67108864L;
    float* qh   = S + 136314880L;
    float* kh   = S + 138412032L;
    float* qk   = S + 140509184L;
    float* h    = S + 174063616L;
    float* h2   = S + 207618048L;
    float* obuf = S + 224395264L;
    float* yn   = S + 241172480L;
    float* f1   = S + 257949696L;
    float* cc   = S + 291504128L;
    float* qq   = S + 291520512L;
    float* vT   = S + 291536896L;
    float* wtv  = S + 325091328L;
    float* wtm  = S + 327188480L;
    float* wth  = S + 331513856L;
    float* wtf1 = S + 333611008L;
    float* wtf2 = S + 335708160L;

    dim3 tb(32,8);

    // norm1 + EMA branch
    layernorm_k<<<BLROWS, 256>>>(x, n1w, n1b, xn);
    emacoef_k<<<64, 256>>>(e_delta, e_alpha, e_beta, e_gamma, cc, qq);
    emascan_k<<<dim3(D_/256, L_/ECHUNK, B_), 256>>>(xn, cc, qq, e_omega, mx);

    // weight transposes -> [N, K] K-major B operands
    transpose_k<<<dim3(V_/32, D_/32, 1), tb>>>(vproj_w, wtv, D_, V_, 0, 0);
    transpose_k<<<dim3(MXCOLS/32, D_/32, 1), tb>>>(mx_w, wtm, D_, MXCOLS, 0, 0);
    transpose_k<<<dim3(D_/32, V_/32, 1), tb>>>(h_w, wth, V_, D_, 0, 0);
    transpose_k<<<dim3((2*D_)/32, D_/32, 1), tb>>>(ff_w1, wtf1, D_, 2*D_, 0, 0);
    transpose_k<<<dim3(D_/32, (2*D_)/32, 1), tb>>>(ff_w2, wtf2, 2*D_, D_, 0, 0);

    // v = silu(xn @ vproj_w + b); then vT per batch for the attn*v GEMM
    gemm_mma<EPI_SILU,true,false><<<dim3(V_/128, BLROWS/128, 1), 256>>>(
        xn, wtv, v, BLROWS, V_, D_, 0,0,0, vproj_b, nullptr, 0);
    transpose_k<<<dim3(V_/32, L_/32, B_), tb>>>(v, vT, L_, V_, (long)L_*V_, (long)V_*L_);

    // base = mx @ mx_w + b
    gemm_mma<EPI_STORE,true,false><<<dim3(MXCOLS/128, BLROWS/128, 1), 256>>>(
        mx, wtm, base, BLROWS, MXCOLS, D_, 0,0,0, mx_b, nullptr, 0);

    // attention
    qhkh_k<<<(long)BLROWS*Z_/256, 256>>>(base, att_g, att_b, qh, kh);
    gemm_mma<EPI_RELBIAS,true,false><<<dim3(L_/128, L_/128, B_), 256>>>(
        qh, kh, qk, L_, L_, Z_,
        (long)L_*Z_, (long)L_*Z_, (long)L_*L_, rel_b, nullptr, 0);
    softmax_k<<<BLROWS, 256>>>(qk);
    gemm_mma<EPI_STORE,false,false><<<dim3(V_/128, L_/128, B_), 256>>>(
        qk, vT, h, L_, V_, L_,
        (long)L_*L_, (long)V_*L_, (long)L_*V_, nullptr, nullptr, 0);

    // h2 = silu(hx + (h*silu(r)) @ h_w + h_b)
    hr_k<<<BLROWS*(V_/256), 256>>>(h, base);
    gemm_mma<EPI_SILU,true,true><<<dim3(D_/128, BLROWS/128, 1), 256>>>(
        h, wth, h2, BLROWS, D_, V_, 0,0,0, h_b, base + (D_+Z_+V_), MXCOLS);

    // out = x + u*(h2 - x)
    outk<<<BLROWS*(D_/256), 256>>>(x, base, h2, obuf);

    // FFN
    layernorm_k<<<BLROWS, 256>>>(obuf, n2w, n2b, yn);
    gemm_mma<EPI_SILU,true,false><<<dim3((2*D_)/128, BLROWS/128, 1), 256>>>(
        yn, wtf1, f1, BLROWS, 2*D_, D_, 0,0,0, ff_b1, nullptr, 0);
    gemm_mma<EPI_STORE,true,true><<<dim3(D_/128, BLROWS/128, 1), 256>>>(
        f1, wtf2, outp, BLROWS, D_, 2*D_, 0,0,0, ff_b2, obuf, D_);
}